// round 1
// baseline (speedup 1.0000x reference)
#include <cuda_runtime.h>
#include <math.h>

#define Bn 4
#define Sn 1024
#define Hn 768
#define NH 12
#define DH 64
#define NEGV (-100000.0f)

#define OUT_ELEMS (Bn * Sn * Hn)            // 3145728
#define QKV_ELEMS (Bn * NH * Sn * DH)       // 3145728 per tensor

// Scratch (static device globals — allowed; no runtime allocation)
__device__ float g_q[QKV_ELEMS];
__device__ float g_k[QKV_ELEMS];
__device__ float g_v[QKV_ELEMS];

// ---------------------------------------------------------------------------
// Kernel 1: fused positional-add + QKV projection GEMM
//   x = (hidden|context) + (s < feat_len ? vis_position : 0)
//   out[o] = x @ W^T + b   (W row-major [o][i], dot over i -> both K-major)
// Tile: BM=128 (s), BN=128 (o), BK=32.  256 threads, 8x8 micro-tile.
// Thread n-columns strided by 16 => conflict-free padded smem frag loads.
// Output written head-interleaved: [b][h][s][d]
// ---------------------------------------------------------------------------
__global__ __launch_bounds__(256) void qkv_kernel(
    const float* __restrict__ hidden, const float* __restrict__ context,
    const float* __restrict__ vis,
    const float* __restrict__ Wq, const float* __restrict__ bq,
    const float* __restrict__ Wk, const float* __restrict__ bk,
    const float* __restrict__ Wv, const float* __restrict__ bv,
    const int*   __restrict__ feat_len)
{
    __shared__ float As[128][33];   // [m][k], pad 33 -> bank (m + k) % 32
    __shared__ float Bs[128][33];   // [n][k]

    const int z     = blockIdx.z;        // b*3 + which
    const int b     = z / 3;
    const int which = z - b * 3;

    const float* X    = (which == 0) ? hidden : context;
    const float* W    = (which == 0) ? Wq : (which == 1 ? Wk : Wv);
    const float* bias = (which == 0) ? bq : (which == 1 ? bk : bv);
    float*       OUT  = (which == 0) ? g_q : (which == 1 ? g_k : g_v);

    const int flen = feat_len[b];
    const int r0 = blockIdx.x << 7;      // s base
    const int c0 = blockIdx.y << 7;      // o base
    const int tid = threadIdx.x;

    const float* Xb = X   + (size_t)b * Sn * Hn;
    const float* Vb = vis + (size_t)b * Sn * Hn;

    const int trow = (tid >> 4) << 3;    // row base of micro-tile (8 rows)
    const int tc   = tid & 15;           // col lane; cols = tc + 16*j

    float acc[8][8];
#pragma unroll
    for (int i = 0; i < 8; i++)
#pragma unroll
        for (int j = 0; j < 8; j++) acc[i][j] = 0.0f;

    for (int k0 = 0; k0 < Hn; k0 += 32) {
        // Load A tile (with fused positional add) and B tile. 1024 float4 each.
#pragma unroll
        for (int it = 0; it < 4; it++) {
            int idx = tid + (it << 8);        // 0..1023 float4 slots
            int row = idx >> 3;               // 8 float4 per 32-wide row
            int c4  = (idx & 7) << 2;
            int s   = r0 + row;
            float4 xv = *(const float4*)(Xb + (size_t)s * Hn + k0 + c4);
            if (s < flen) {
                float4 vv = *(const float4*)(Vb + (size_t)s * Hn + k0 + c4);
                xv.x += vv.x; xv.y += vv.y; xv.z += vv.z; xv.w += vv.w;
            }
            As[row][c4 + 0] = xv.x; As[row][c4 + 1] = xv.y;
            As[row][c4 + 2] = xv.z; As[row][c4 + 3] = xv.w;

            int o = c0 + row;
            float4 wv = *(const float4*)(W + (size_t)o * Hn + k0 + c4);
            Bs[row][c4 + 0] = wv.x; Bs[row][c4 + 1] = wv.y;
            Bs[row][c4 + 2] = wv.z; Bs[row][c4 + 3] = wv.w;
        }
        __syncthreads();

#pragma unroll 8
        for (int k = 0; k < 32; k++) {
            float a[8], bb[8];
#pragma unroll
            for (int i = 0; i < 8; i++) a[i] = As[trow + i][k];
#pragma unroll
            for (int j = 0; j < 8; j++) bb[j] = Bs[tc + (j << 4)][k];
#pragma unroll
            for (int i = 0; i < 8; i++)
#pragma unroll
                for (int j = 0; j < 8; j++) acc[i][j] = fmaf(a[i], bb[j], acc[i][j]);
        }
        __syncthreads();
    }

    // Epilogue: bias + head-interleaved store [b][h][s][d]
#pragma unroll
    for (int j = 0; j < 8; j++) {
        int o  = c0 + tc + (j << 4);
        float bo = bias[o];
        int h = o >> 6, d = o & 63;
        size_t base = (((size_t)b * NH + h) * Sn) * DH + d;
#pragma unroll
        for (int i = 0; i < 8; i++) {
            int s = r0 + trow + i;
            OUT[base + (size_t)s * DH] = acc[i][j] + bo;
        }
    }
}

// ---------------------------------------------------------------------------
// Kernel 2: scores = mask_apply( (q @ k^T) / 8 * gate + amask )
// Per (b,h): M=N=1024, K=64 (single K tile). 128x128 tile, 8x8 micro-tile.
// Dynamic smem: Qs[128][65] + Ks[128][65] = 66560 B.
// ---------------------------------------------------------------------------
__global__ __launch_bounds__(256) void scores_kernel(
    const float* __restrict__ gate, const float* __restrict__ amask,
    const int*   __restrict__ feat_len, const int* __restrict__ prox_ptr,
    float* __restrict__ scores)
{
    extern __shared__ float smem[];
    float (*Qs)[65] = (float (*)[65])smem;
    float (*Ks)[65] = (float (*)[65])(smem + 128 * 65);

    const int bh = blockIdx.z;
    const int b  = bh / NH;
    const int r0 = blockIdx.x << 7;
    const int c0 = blockIdx.y << 7;
    const int tid = threadIdx.x;
    const int P    = prox_ptr[0];
    const int flen = feat_len[b];

    const float* Q = g_q + (size_t)bh * Sn * DH;
    const float* K = g_k + (size_t)bh * Sn * DH;

    // Load 128x64 tiles of Q and K (2048 float4 each / 256 threads = 8 iters)
#pragma unroll
    for (int it = 0; it < 8; it++) {
        int idx = tid + (it << 8);
        int row = idx >> 4;
        int c4  = (idx & 15) << 2;
        float4 qv = *(const float4*)(Q + (size_t)(r0 + row) * DH + c4);
        Qs[row][c4 + 0] = qv.x; Qs[row][c4 + 1] = qv.y;
        Qs[row][c4 + 2] = qv.z; Qs[row][c4 + 3] = qv.w;
        float4 kv = *(const float4*)(K + (size_t)(c0 + row) * DH + c4);
        Ks[row][c4 + 0] = kv.x; Ks[row][c4 + 1] = kv.y;
        Ks[row][c4 + 2] = kv.z; Ks[row][c4 + 3] = kv.w;
    }
    __syncthreads();

    const int trow = (tid >> 4) << 3;
    const int tc   = tid & 15;

    float acc[8][8];
#pragma unroll
    for (int i = 0; i < 8; i++)
#pragma unroll
        for (int j = 0; j < 8; j++) acc[i][j] = 0.0f;

#pragma unroll 8
    for (int k = 0; k < 64; k++) {
        float a[8], bb[8];
#pragma unroll
        for (int i = 0; i < 8; i++) a[i] = Qs[trow + i][k];
#pragma unroll
        for (int j = 0; j < 8; j++) bb[j] = Ks[tc + (j << 4)][k];
#pragma unroll
        for (int i = 0; i < 8; i++)
#pragma unroll
            for (int j = 0; j < 8; j++) acc[i][j] = fmaf(a[i], bb[j], acc[i][j]);
    }

    // Epilogue: scale, gate, additive mask, structural masking, store
    const float* gate_b = gate + (size_t)b * Sn * Sn;
    const float* am_b   = amask + (size_t)b * Sn;
    float* sc_out = scores + (size_t)bh * Sn * Sn;

#pragma unroll
    for (int i = 0; i < 8; i++) {
        int r = r0 + trow + i;
        bool rband = (r < P - 1);
        bool rge   = (r >= P);
#pragma unroll
        for (int j = 0; j < 8; j++) {
            int c = c0 + tc + (j << 4);
            float val = acc[i][j] * 0.125f;
            val = val * gate_b[(size_t)r * Sn + c] + am_b[c];
            bool blk  = rge && (c >= P);
            bool band = rband && ((c > r) || (c < r - 1));
            bool m3   = rge && (c < flen - 1);
            if (blk || band || m3) val = NEGV;
            sc_out[(size_t)r * Sn + c] = val;
        }
    }
}

// ---------------------------------------------------------------------------
// Kernel 3: row softmax over scores + PV + output store
// Block = (b, h, 32-row slab). 256 threads.
// Pass 1: rowmax (needed: fully-masked rows are all -1e5 -> exp(0)=1 uniform).
// Pass 2: stream 32-col chunks: p = expf(s - max) -> smem, accumulate rowsum
//         and O += p @ v.  Normalize at end.
// ---------------------------------------------------------------------------
__global__ __launch_bounds__(256) void softmax_pv_kernel(
    const float* __restrict__ scores, float* __restrict__ out)
{
    const int rb = blockIdx.x;            // 32-row slab
    const int h  = blockIdx.y;
    const int b  = blockIdx.z;
    const int bh = b * NH + h;
    const int r0 = rb << 5;

    const float* sc = scores + ((size_t)bh * Sn + r0) * Sn;
    const float* V  = g_v + (size_t)bh * Sn * DH;

    const int tid  = threadIdx.x;
    const int lane = tid & 31;
    const int w    = tid >> 5;

    __shared__ float pbuf[32][33];
    __shared__ float vtile[32][64];
    __shared__ float rowmax[32];
    __shared__ float rowsum[32];

    // Pass 1: row maxima. Warp w handles rows w, w+8, w+16, w+24.
#pragma unroll
    for (int rr = w; rr < 32; rr += 8) {
        float m = -INFINITY;
        const float* row = sc + (size_t)rr * Sn;
#pragma unroll 8
        for (int c = lane; c < Sn; c += 32) m = fmaxf(m, row[c]);
#pragma unroll
        for (int off = 16; off > 0; off >>= 1)
            m = fmaxf(m, __shfl_xor_sync(0xffffffffu, m, off));
        if (lane == 0) rowmax[rr] = m;
    }
    __syncthreads();

    // Per-thread exp rows: row = w + 8*ii, col = lane  (within 32-col chunk)
    float rm[4];
#pragma unroll
    for (int ii = 0; ii < 4; ii++) rm[ii] = rowmax[w + 8 * ii];
    float psum[4] = {0.f, 0.f, 0.f, 0.f};

    // PV mapping: thread -> (row pr, 8 contiguous d starting at pd)
    const int pr = tid >> 3;
    const int pd = (tid & 7) << 3;
    float acc[8] = {0.f, 0.f, 0.f, 0.f, 0.f, 0.f, 0.f, 0.f};

    for (int cb = 0; cb < Sn; cb += 32) {
        // Load V chunk 32x64 (512 float4 / 256 threads = 2 iters)
#pragma unroll
        for (int it = 0; it < 2; it++) {
            int idx = tid + (it << 8);
            int row = idx >> 4, c4 = (idx & 15) << 2;
            *(float4*)&vtile[row][c4] =
                *(const float4*)(V + (size_t)(cb + row) * DH + c4);
        }
        // p chunk: 1024 elems / 256 threads = 4
#pragma unroll
        for (int ii = 0; ii < 4; ii++) {
            int row = w + 8 * ii;
            float s = sc[(size_t)row * Sn + cb + lane];
            float p = __expf(s - rm[ii]);
            pbuf[row][lane] = p;
            psum[ii] += p;
        }
        __syncthreads();

#pragma unroll
        for (int cc = 0; cc < 32; cc++) {
            float p  = pbuf[pr][cc];
            float4 v0 = *(const float4*)&vtile[cc][pd];
            float4 v1 = *(const float4*)&vtile[cc][pd + 4];
            acc[0] = fmaf(p, v0.x, acc[0]); acc[1] = fmaf(p, v0.y, acc[1]);
            acc[2] = fmaf(p, v0.z, acc[2]); acc[3] = fmaf(p, v0.w, acc[3]);
            acc[4] = fmaf(p, v1.x, acc[4]); acc[5] = fmaf(p, v1.y, acc[5]);
            acc[6] = fmaf(p, v1.z, acc[6]); acc[7] = fmaf(p, v1.w, acc[7]);
        }
        __syncthreads();
    }

    // Reduce row sums (32 lanes of warp w hold partials for row w+8*ii)
#pragma unroll
    for (int ii = 0; ii < 4; ii++) {
        float s = psum[ii];
#pragma unroll
        for (int off = 16; off > 0; off >>= 1)
            s += __shfl_xor_sync(0xffffffffu, s, off);
        if (lane == 0) rowsum[w + 8 * ii] = s;
    }
    __syncthreads();

    const float inv = 1.0f / rowsum[pr];
    const int sg = r0 + pr;
    float* o = out + ((size_t)b * Sn + sg) * Hn + h * DH + pd;
    float4 o0 = make_float4(acc[0] * inv, acc[1] * inv, acc[2] * inv, acc[3] * inv);
    float4 o1 = make_float4(acc[4] * inv, acc[5] * inv, acc[6] * inv, acc[7] * inv);
    *(float4*)o       = o0;
    *(float4*)(o + 4) = o1;
}

// ---------------------------------------------------------------------------
extern "C" void kernel_launch(void* const* d_in, const int* in_sizes, int n_in,
                              void* d_out, int out_size)
{
    const float* hidden  = (const float*)d_in[0];
    const float* context = (const float*)d_in[1];
    const float* amask   = (const float*)d_in[2];
    const float* gate    = (const float*)d_in[3];
    const float* vis     = (const float*)d_in[4];
    const float* Wq      = (const float*)d_in[5];
    const float* bq      = (const float*)d_in[6];
    const float* Wk      = (const float*)d_in[7];
    const float* bk      = (const float*)d_in[8];
    const float* Wv      = (const float*)d_in[9];
    const float* bv      = (const float*)d_in[10];
    const int*   feat    = (const int*)d_in[11];
    const int*   proxp   = (const int*)d_in[12];

    float* out    = (float*)d_out;
    float* scores = out + OUT_ELEMS;

    // Attribute set is host-side (not a stream op) -> capture-safe, deterministic.
    static bool attr_done = false;
    (void)attr_done;
    cudaFuncSetAttribute(scores_kernel,
                         cudaFuncAttributeMaxDynamicSharedMemorySize,
                         2 * 128 * 65 * (int)sizeof(float));

    qkv_kernel<<<dim3(Sn / 128, Hn / 128, Bn * 3), 256>>>(
        hidden, context, vis, Wq, bq, Wk, bk, Wv, bv, feat);

    scores_kernel<<<dim3(Sn / 128, Sn / 128, Bn * NH), 256,
                    2 * 128 * 65 * sizeof(float)>>>(
        gate, amask, feat, proxp, scores);

    softmax_pv_kernel<<<dim3(Sn / 32, NH, Bn), 256>>>(scores, out);
}

// round 3
// speedup vs baseline: 1.9091x; 1.9091x over previous
#include <cuda_runtime.h>
#include <math.h>

#define Bn 4
#define Sn 1024
#define Hn 768
#define NH 12
#define DH 64
#define NEGV (-100000.0f)

#define OUT_ELEMS (Bn * Sn * Hn)            // 3145728
#define QKV_ELEMS (Bn * NH * Sn * DH)       // 3145728 per tensor

// Scratch (static device globals — allowed; no runtime allocation)
__device__ float g_q[QKV_ELEMS];
__device__ float g_k[QKV_ELEMS];
__device__ float g_v[QKV_ELEMS];

// ---------------------------------------------------------------------------
// Kernel 1: fused positional-add + QKV projection GEMM
//   x = (hidden|context) + (s < feat_len ? vis_position : 0)
//   out[o] = x @ W^T + b
// Tile: BM=128, BN=128, BK=32. 256 threads, 8x8 micro-tile.
// ---------------------------------------------------------------------------
__global__ __launch_bounds__(256) void qkv_kernel(
    const float* __restrict__ hidden, const float* __restrict__ context,
    const float* __restrict__ vis,
    const float* __restrict__ Wq, const float* __restrict__ bq,
    const float* __restrict__ Wk, const float* __restrict__ bk,
    const float* __restrict__ Wv, const float* __restrict__ bv,
    const int*   __restrict__ feat_len)
{
    __shared__ float As[128][33];
    __shared__ float Bs[128][33];

    const int z     = blockIdx.z;
    const int b     = z / 3;
    const int which = z - b * 3;

    const float* X    = (which == 0) ? hidden : context;
    const float* W    = (which == 0) ? Wq : (which == 1 ? Wk : Wv);
    const float* bias = (which == 0) ? bq : (which == 1 ? bk : bv);
    float*       OUT  = (which == 0) ? g_q : (which == 1 ? g_k : g_v);

    const int flen = feat_len[b];
    const int r0 = blockIdx.x << 7;
    const int c0 = blockIdx.y << 7;
    const int tid = threadIdx.x;

    const float* Xb = X   + (size_t)b * Sn * Hn;
    const float* Vb = vis + (size_t)b * Sn * Hn;

    const int trow = (tid >> 4) << 3;
    const int tc   = tid & 15;

    float acc[8][8];
#pragma unroll
    for (int i = 0; i < 8; i++)
#pragma unroll
        for (int j = 0; j < 8; j++) acc[i][j] = 0.0f;

    for (int k0 = 0; k0 < Hn; k0 += 32) {
#pragma unroll
        for (int it = 0; it < 4; it++) {
            int idx = tid + (it << 8);
            int row = idx >> 3;
            int c4  = (idx & 7) << 2;
            int s   = r0 + row;
            float4 xv = *(const float4*)(Xb + (size_t)s * Hn + k0 + c4);
            if (s < flen) {
                float4 vv = *(const float4*)(Vb + (size_t)s * Hn + k0 + c4);
                xv.x += vv.x; xv.y += vv.y; xv.z += vv.z; xv.w += vv.w;
            }
            As[row][c4 + 0] = xv.x; As[row][c4 + 1] = xv.y;
            As[row][c4 + 2] = xv.z; As[row][c4 + 3] = xv.w;

            int o = c0 + row;
            float4 wv = *(const float4*)(W + (size_t)o * Hn + k0 + c4);
            Bs[row][c4 + 0] = wv.x; Bs[row][c4 + 1] = wv.y;
            Bs[row][c4 + 2] = wv.z; Bs[row][c4 + 3] = wv.w;
        }
        __syncthreads();

#pragma unroll 8
        for (int k = 0; k < 32; k++) {
            float a[8], bb[8];
#pragma unroll
            for (int i = 0; i < 8; i++) a[i] = As[trow + i][k];
#pragma unroll
            for (int j = 0; j < 8; j++) bb[j] = Bs[tc + (j << 4)][k];
#pragma unroll
            for (int i = 0; i < 8; i++)
#pragma unroll
                for (int j = 0; j < 8; j++) acc[i][j] = fmaf(a[i], bb[j], acc[i][j]);
        }
        __syncthreads();
    }

#pragma unroll
    for (int j = 0; j < 8; j++) {
        int o  = c0 + tc + (j << 4);
        float bo = bias[o];
        int h = o >> 6, d = o & 63;
        size_t base = (((size_t)b * NH + h) * Sn) * DH + d;
#pragma unroll
        for (int i = 0; i < 8; i++) {
            int s = r0 + trow + i;
            OUT[base + (size_t)s * DH] = acc[i][j] + bo;
        }
    }
}

// ---------------------------------------------------------------------------
// Kernel 2: fused scores + online softmax + PV  (flash-attention style)
//
// Block = (b,h, 64-row tile). 256 threads. Loops over 8 col-tiles of 128.
// Per tile: S = Q·K^T (regs, 4x8 frag) -> epilogue (gate/mask) -> write
// scores to gmem (required output) -> online softmax (shfl over the 16-lane
// row group) -> P halves staged in smem -> PV accumulate (4x4 O frag).
//
// Smem: Qs[64][65] + Ks[128][65] + Vs[128][68] + Ps[64][65] = 101376 B
//   -> 2 blocks/SM with <=128 regs (launch_bounds(256,2)).
// ---------------------------------------------------------------------------
#define QS_OFF 0
#define KS_OFF (64 * 65)
#define VS_OFF (KS_OFF + 128 * 65)
#define PS_OFF (VS_OFF + 128 * 68)
#define ATTN_SMEM ((PS_OFF + 64 * 65) * sizeof(float))

__global__ __launch_bounds__(256, 2) void attn_kernel(
    const float* __restrict__ gate, const float* __restrict__ amask,
    const int*   __restrict__ feat_len, const int* __restrict__ prox_ptr,
    float* __restrict__ scores, float* __restrict__ out)
{
    extern __shared__ float sm[];
    float (*Qs)[65] = (float (*)[65])(sm + QS_OFF);
    float (*Ks)[65] = (float (*)[65])(sm + KS_OFF);
    float (*Vs)[68] = (float (*)[68])(sm + VS_OFF);
    float (*Ps)[65] = (float (*)[65])(sm + PS_OFF);

    const int bh = blockIdx.y;
    const int b  = bh / NH;
    const int h  = bh - b * NH;
    const int r0 = blockIdx.x << 6;          // 64-row tile
    const int tid = threadIdx.x;
    const int tr  = tid >> 4;                // 0..15
    const int tc  = tid & 15;                // 0..15
    const int trow = tr << 2;                // 4 rows per thread

    const int P    = prox_ptr[0];
    const int flen = feat_len[b];

    const float* Q = g_q + (size_t)bh * Sn * DH;
    const float* K = g_k + (size_t)bh * Sn * DH;
    const float* V = g_v + (size_t)bh * Sn * DH;
    const float* gate_b = gate + (size_t)b * Sn * Sn;
    const float* am_b   = amask + (size_t)b * Sn;
    float* sc_out = scores + (size_t)bh * Sn * Sn;

    // ---- Load Q tile 64x64 ----
#pragma unroll
    for (int it = 0; it < 4; it++) {
        int idx = tid + (it << 8);
        int row = idx >> 4;
        int c4  = (idx & 15) << 2;
        float4 qv = *(const float4*)(Q + (size_t)(r0 + row) * DH + c4);
        Qs[row][c4 + 0] = qv.x; Qs[row][c4 + 1] = qv.y;
        Qs[row][c4 + 2] = qv.z; Qs[row][c4 + 3] = qv.w;
    }

    float m_i[4], l_i[4];
    float o_acc[4][4];
#pragma unroll
    for (int i = 0; i < 4; i++) {
        m_i[i] = -INFINITY; l_i[i] = 0.0f;
#pragma unroll
        for (int j = 0; j < 4; j++) o_acc[i][j] = 0.0f;
    }

    for (int cb = 0; cb < Sn; cb += 128) {
        // ---- Load K,V tiles 128x64 ----
        __syncthreads();   // previous PV done reading Vs/Ks
#pragma unroll
        for (int it = 0; it < 8; it++) {
            int idx = tid + (it << 8);
            int row = idx >> 4;
            int c4  = (idx & 15) << 2;
            float4 kv = *(const float4*)(K + (size_t)(cb + row) * DH + c4);
            Ks[row][c4 + 0] = kv.x; Ks[row][c4 + 1] = kv.y;
            Ks[row][c4 + 2] = kv.z; Ks[row][c4 + 3] = kv.w;
            float4 vv = *(const float4*)(V + (size_t)(cb + row) * DH + c4);
            *(float4*)&Vs[row][c4] = vv;
        }
        __syncthreads();

        // ---- S = Q K^T : 4x8 frag ----
        float acc[4][8];
#pragma unroll
        for (int i = 0; i < 4; i++)
#pragma unroll
            for (int j = 0; j < 8; j++) acc[i][j] = 0.0f;

#pragma unroll 8
        for (int k = 0; k < DH; k++) {
            float a[4], bb[8];
#pragma unroll
            for (int i = 0; i < 4; i++) a[i] = Qs[trow + i][k];
#pragma unroll
            for (int j = 0; j < 8; j++) bb[j] = Ks[tc + (j << 4)][k];
#pragma unroll
            for (int i = 0; i < 4; i++)
#pragma unroll
                for (int j = 0; j < 8; j++) acc[i][j] = fmaf(a[i], bb[j], acc[i][j]);
        }

        // ---- epilogue: scale*gate + amask, structural masks, write scores ----
#pragma unroll
        for (int i = 0; i < 4; i++) {
            int r = r0 + trow + i;
            bool rband = (r < P - 1);
            bool rge   = (r >= P);
            const float* grow = gate_b + (size_t)r * Sn;
            float* srow = sc_out + (size_t)r * Sn;
#pragma unroll
            for (int j = 0; j < 8; j++) {
                int c = cb + tc + (j << 4);
                float val = acc[i][j] * 0.125f;
                val = val * grow[c] + am_b[c];
                bool blk  = rge && (c >= P);
                bool band = rband && ((c > r) || (c < r - 1));
                bool m3   = rge && (c < flen - 1);
                if (blk || band || m3) val = NEGV;
                acc[i][j] = val;
                srow[c] = val;
            }
        }

        // ---- online softmax update ----
#pragma unroll
        for (int i = 0; i < 4; i++) {
            float tmax = acc[i][0];
#pragma unroll
            for (int j = 1; j < 8; j++) tmax = fmaxf(tmax, acc[i][j]);
#pragma unroll
            for (int off = 8; off > 0; off >>= 1)
                tmax = fmaxf(tmax, __shfl_xor_sync(0xffffffffu, tmax, off));
            float m_new = fmaxf(m_i[i], tmax);
            float corr  = __expf(m_i[i] - m_new);   // 0 on first tile (-inf)
            m_i[i] = m_new;
            float psum = 0.0f;
#pragma unroll
            for (int j = 0; j < 8; j++) {
                float p = __expf(acc[i][j] - m_new);
                acc[i][j] = p;
                psum += p;
            }
#pragma unroll
            for (int off = 8; off > 0; off >>= 1)
                psum += __shfl_xor_sync(0xffffffffu, psum, off);
            l_i[i] = l_i[i] * corr + psum;
#pragma unroll
            for (int j = 0; j < 4; j++) o_acc[i][j] *= corr;
        }

        // ---- PV in two 64-col halves ----
#pragma unroll
        for (int half = 0; half < 2; half++) {
            __syncthreads();   // prior PV reads of Ps complete
#pragma unroll
            for (int i = 0; i < 4; i++)
#pragma unroll
                for (int j = 0; j < 4; j++)
                    Ps[trow + i][tc + (j << 4)] = acc[i][(half << 2) + j];
            __syncthreads();

            const int vb = half << 6;
#pragma unroll 8
            for (int cc = 0; cc < 64; cc++) {
                float pa[4];
#pragma unroll
                for (int i = 0; i < 4; i++) pa[i] = Ps[trow + i][cc];
                float4 vv = *(const float4*)&Vs[vb + cc][tc << 2];
#pragma unroll
                for (int i = 0; i < 4; i++) {
                    o_acc[i][0] = fmaf(pa[i], vv.x, o_acc[i][0]);
                    o_acc[i][1] = fmaf(pa[i], vv.y, o_acc[i][1]);
                    o_acc[i][2] = fmaf(pa[i], vv.z, o_acc[i][2]);
                    o_acc[i][3] = fmaf(pa[i], vv.w, o_acc[i][3]);
                }
            }
        }
    }

    // ---- finalize: normalize and store out[b][s][h*64 + d] ----
#pragma unroll
    for (int i = 0; i < 4; i++) {
        float inv = 1.0f / l_i[i];
        int s = r0 + trow + i;
        float* o = out + ((size_t)b * Sn + s) * Hn + h * DH + (tc << 2);
        float4 ov = make_float4(o_acc[i][0] * inv, o_acc[i][1] * inv,
                                o_acc[i][2] * inv, o_acc[i][3] * inv);
        *(float4*)o = ov;
    }
}

// ---------------------------------------------------------------------------
extern "C" void kernel_launch(void* const* d_in, const int* in_sizes, int n_in,
                              void* d_out, int out_size)
{
    const float* hidden  = (const float*)d_in[0];
    const float* context = (const float*)d_in[1];
    const float* amask   = (const float*)d_in[2];
    const float* gate    = (const float*)d_in[3];
    const float* vis     = (const float*)d_in[4];
    const float* Wq      = (const float*)d_in[5];
    const float* bq      = (const float*)d_in[6];
    const float* Wk      = (const float*)d_in[7];
    const float* bk      = (const float*)d_in[8];
    const float* Wv      = (const float*)d_in[9];
    const float* bv      = (const float*)d_in[10];
    const int*   feat    = (const int*)d_in[11];
    const int*   proxp   = (const int*)d_in[12];

    float* out    = (float*)d_out;
    float* scores = out + OUT_ELEMS;

    cudaFuncSetAttribute(attn_kernel,
                         cudaFuncAttributeMaxDynamicSharedMemorySize,
                         (int)ATTN_SMEM);

    qkv_kernel<<<dim3(Sn / 128, Hn / 128, Bn * 3), 256>>>(
        hidden, context, vis, Wq, bq, Wk, bk, Wv, bv, feat);

    attn_kernel<<<dim3(Sn / 64, Bn * NH), 256, ATTN_SMEM>>>(
        gate, amask, feat, proxp, scores, out);
}

// round 4
// speedup vs baseline: 1.9258x; 1.0087x over previous
#include <cuda_runtime.h>
#include <math.h>

#define Bn 4
#define Sn 1024
#define Hn 768
#define NH 12
#define DH 64
#define NEGV (-100000.0f)

#define OUT_ELEMS (Bn * Sn * Hn)            // 3145728
#define QKV_ELEMS (Bn * NH * Sn * DH)       // 3145728 per tensor

// Scratch (static device globals — allowed; no runtime allocation)
__device__ float g_q[QKV_ELEMS];
__device__ float g_k[QKV_ELEMS];
__device__ float g_v[QKV_ELEMS];

// ---------------------------------------------------------------------------
// Kernel 1: fused positional-add + QKV projection GEMM (unchanged — 55% fma)
// ---------------------------------------------------------------------------
__global__ __launch_bounds__(256) void qkv_kernel(
    const float* __restrict__ hidden, const float* __restrict__ context,
    const float* __restrict__ vis,
    const float* __restrict__ Wq, const float* __restrict__ bq,
    const float* __restrict__ Wk, const float* __restrict__ bk,
    const float* __restrict__ Wv, const float* __restrict__ bv,
    const int*   __restrict__ feat_len)
{
    __shared__ float As[128][33];
    __shared__ float Bs[128][33];

    const int z     = blockIdx.z;
    const int b     = z / 3;
    const int which = z - b * 3;

    const float* X    = (which == 0) ? hidden : context;
    const float* W    = (which == 0) ? Wq : (which == 1 ? Wk : Wv);
    const float* bias = (which == 0) ? bq : (which == 1 ? bk : bv);
    float*       OUT  = (which == 0) ? g_q : (which == 1 ? g_k : g_v);

    const int flen = feat_len[b];
    const int r0 = blockIdx.x << 7;
    const int c0 = blockIdx.y << 7;
    const int tid = threadIdx.x;

    const float* Xb = X   + (size_t)b * Sn * Hn;
    const float* Vb = vis + (size_t)b * Sn * Hn;

    const int trow = (tid >> 4) << 3;
    const int tc   = tid & 15;

    float acc[8][8];
#pragma unroll
    for (int i = 0; i < 8; i++)
#pragma unroll
        for (int j = 0; j < 8; j++) acc[i][j] = 0.0f;

    for (int k0 = 0; k0 < Hn; k0 += 32) {
#pragma unroll
        for (int it = 0; it < 4; it++) {
            int idx = tid + (it << 8);
            int row = idx >> 3;
            int c4  = (idx & 7) << 2;
            int s   = r0 + row;
            float4 xv = *(const float4*)(Xb + (size_t)s * Hn + k0 + c4);
            if (s < flen) {
                float4 vv = *(const float4*)(Vb + (size_t)s * Hn + k0 + c4);
                xv.x += vv.x; xv.y += vv.y; xv.z += vv.z; xv.w += vv.w;
            }
            As[row][c4 + 0] = xv.x; As[row][c4 + 1] = xv.y;
            As[row][c4 + 2] = xv.z; As[row][c4 + 3] = xv.w;

            int o = c0 + row;
            float4 wv = *(const float4*)(W + (size_t)o * Hn + k0 + c4);
            Bs[row][c4 + 0] = wv.x; Bs[row][c4 + 1] = wv.y;
            Bs[row][c4 + 2] = wv.z; Bs[row][c4 + 3] = wv.w;
        }
        __syncthreads();

#pragma unroll 8
        for (int k = 0; k < 32; k++) {
            float a[8], bb[8];
#pragma unroll
            for (int i = 0; i < 8; i++) a[i] = As[trow + i][k];
#pragma unroll
            for (int j = 0; j < 8; j++) bb[j] = Bs[tc + (j << 4)][k];
#pragma unroll
            for (int i = 0; i < 8; i++)
#pragma unroll
                for (int j = 0; j < 8; j++) acc[i][j] = fmaf(a[i], bb[j], acc[i][j]);
        }
        __syncthreads();
    }

#pragma unroll
    for (int j = 0; j < 8; j++) {
        int o  = c0 + tc + (j << 4);
        float bo = bias[o];
        int h = o >> 6, d = o & 63;
        size_t base = (((size_t)b * NH + h) * Sn) * DH + d;
#pragma unroll
        for (int i = 0; i < 8; i++) {
            int s = r0 + trow + i;
            OUT[base + (size_t)s * DH] = acc[i][j] + bo;
        }
    }
}

// ---------------------------------------------------------------------------
// Kernel 2 (v2): fused scores + online softmax + PV, LDS-optimized
//
// Block = (b,h, 128-row tile). 256 threads, 8x8 fragment (rows tr*8+i,
// cols half*64 + tc*4 + j). Q/K stored TRANSPOSED in smem (stride 132) so
// fragment loads are LDS.128. PV uses __shfl_sync P-broadcast (no Ps smem,
// no extra syncs). Epilogue fully vectorized (float4 gate/amask/score/out).
//
// Smem: Qt[64][132] + Kt[64][132] + Vs[128][68] = 102400 B -> 1 block/SM.
// ---------------------------------------------------------------------------
#define ATTN_SMEM ((2 * 64 * 132 + 128 * 68) * sizeof(float))

__global__ __launch_bounds__(256, 1) void attn_kernel(
    const float* __restrict__ gate, const float* __restrict__ amask,
    const int*   __restrict__ feat_len, const int* __restrict__ prox_ptr,
    float* __restrict__ scores, float* __restrict__ out)
{
    extern __shared__ float sm[];
    float (*Qt)[132] = (float (*)[132])(sm);
    float (*Kt)[132] = (float (*)[132])(sm + 64 * 132);
    float (*Vs)[68]  = (float (*)[68]) (sm + 2 * 64 * 132);

    const int bh = blockIdx.y;
    const int b  = bh / NH;
    const int h  = bh - b * NH;
    const int r0 = blockIdx.x << 7;          // 128-row tile
    const int tid  = threadIdx.x;
    const int tr   = tid >> 4;               // 0..15
    const int tc   = tid & 15;               // 0..15
    const int trow = tr << 3;                // 8 rows per thread
    const int lane = tid & 31;
    const int srcbase = lane & 16;           // shfl: stay in own row-group half

    const int P    = prox_ptr[0];
    const int flen = feat_len[b];

    const float* Q = g_q + (size_t)bh * Sn * DH;
    const float* K = g_k + (size_t)bh * Sn * DH;
    const float* V = g_v + (size_t)bh * Sn * DH;
    const float* gate_b = gate + (size_t)b * Sn * Sn;
    const float* am_b   = amask + (size_t)b * Sn;
    float* sc_out = scores + (size_t)bh * Sn * Sn;

    // ---- Load Q tile 128x64, transposed into Qt[k][row] ----
#pragma unroll
    for (int it = 0; it < 8; it++) {
        int idx = tid + (it << 8);
        int row = idx >> 4;
        int c4  = (idx & 15) << 2;
        float4 qv = *(const float4*)(Q + (size_t)(r0 + row) * DH + c4);
        Qt[c4 + 0][row] = qv.x; Qt[c4 + 1][row] = qv.y;
        Qt[c4 + 2][row] = qv.z; Qt[c4 + 3][row] = qv.w;
    }

    float m_i[8], l_i[8];
    float o_acc[8][4];
#pragma unroll
    for (int i = 0; i < 8; i++) {
        m_i[i] = -INFINITY; l_i[i] = 0.0f;
#pragma unroll
        for (int j = 0; j < 4; j++) o_acc[i][j] = 0.0f;
    }

    for (int cb = 0; cb < Sn; cb += 128) {
        __syncthreads();   // prior tile's S-phase (Kt) and PV (Vs) reads done
        // ---- Load K (transposed) and V tiles, 128x64 each ----
#pragma unroll
        for (int it = 0; it < 8; it++) {
            int idx = tid + (it << 8);
            int row = idx >> 4;
            int c4  = (idx & 15) << 2;
            float4 kv = *(const float4*)(K + (size_t)(cb + row) * DH + c4);
            Kt[c4 + 0][row] = kv.x; Kt[c4 + 1][row] = kv.y;
            Kt[c4 + 2][row] = kv.z; Kt[c4 + 3][row] = kv.w;
            float4 vv = *(const float4*)(V + (size_t)(cb + row) * DH + c4);
            *(float4*)&Vs[row][c4] = vv;
        }
        __syncthreads();

        // ---- S = Q K^T : 8x8 frag, vectorized smem reads ----
        float acc[8][8];
#pragma unroll
        for (int i = 0; i < 8; i++)
#pragma unroll
            for (int j = 0; j < 8; j++) acc[i][j] = 0.0f;

#pragma unroll 8
        for (int k = 0; k < DH; k++) {
            float4 a0 = *(const float4*)&Qt[k][trow];
            float4 a1 = *(const float4*)&Qt[k][trow + 4];
            float4 b0 = *(const float4*)&Kt[k][tc << 2];
            float4 b1 = *(const float4*)&Kt[k][64 + (tc << 2)];
            float a[8] = {a0.x, a0.y, a0.z, a0.w, a1.x, a1.y, a1.z, a1.w};
            float bb[8] = {b0.x, b0.y, b0.z, b0.w, b1.x, b1.y, b1.z, b1.w};
#pragma unroll
            for (int i = 0; i < 8; i++)
#pragma unroll
                for (int j = 0; j < 8; j++) acc[i][j] = fmaf(a[i], bb[j], acc[i][j]);
        }

        // ---- epilogue: scale*gate + amask, structural masks, write scores ----
        const float4 am0 = *(const float4*)&am_b[cb + (tc << 2)];
        const float4 am1 = *(const float4*)&am_b[cb + 64 + (tc << 2)];
        const float amv[8] = {am0.x, am0.y, am0.z, am0.w, am1.x, am1.y, am1.z, am1.w};
#pragma unroll
        for (int i = 0; i < 8; i++) {
            int r = r0 + trow + i;
            bool rband = (r < P - 1);
            bool rge   = (r >= P);
            const float* grow = gate_b + (size_t)r * Sn;
            float* srow = sc_out + (size_t)r * Sn;
            float4 g0 = *(const float4*)&grow[cb + (tc << 2)];
            float4 g1 = *(const float4*)&grow[cb + 64 + (tc << 2)];
            float gv[8] = {g0.x, g0.y, g0.z, g0.w, g1.x, g1.y, g1.z, g1.w};
#pragma unroll
            for (int half = 0; half < 2; half++) {
#pragma unroll
                for (int j = 0; j < 4; j++) {
                    int jj = (half << 2) + j;
                    int c = cb + (half << 6) + (tc << 2) + j;
                    float val = acc[i][jj] * 0.125f;
                    val = val * gv[jj] + amv[jj];
                    bool blk  = rge && (c >= P);
                    bool band = rband && ((c > r) || (c < r - 1));
                    bool m3   = rge && (c < flen - 1);
                    if (blk || band || m3) val = NEGV;
                    acc[i][jj] = val;
                }
                float4 sv = make_float4(acc[i][(half << 2) + 0], acc[i][(half << 2) + 1],
                                        acc[i][(half << 2) + 2], acc[i][(half << 2) + 3]);
                *(float4*)&srow[cb + (half << 6) + (tc << 2)] = sv;
            }
        }

        // ---- online softmax update ----
#pragma unroll
        for (int i = 0; i < 8; i++) {
            float tmax = acc[i][0];
#pragma unroll
            for (int j = 1; j < 8; j++) tmax = fmaxf(tmax, acc[i][j]);
#pragma unroll
            for (int off = 8; off > 0; off >>= 1)
                tmax = fmaxf(tmax, __shfl_xor_sync(0xffffffffu, tmax, off));
            float m_new = fmaxf(m_i[i], tmax);
            float corr  = __expf(m_i[i] - m_new);   // 0 on first tile (-inf)
            m_i[i] = m_new;
            float psum = 0.0f;
#pragma unroll
            for (int j = 0; j < 8; j++) {
                float p = __expf(acc[i][j] - m_new);
                acc[i][j] = p;
                psum += p;
            }
#pragma unroll
            for (int off = 8; off > 0; off >>= 1)
                psum += __shfl_xor_sync(0xffffffffu, psum, off);
            l_i[i] = l_i[i] * corr + psum;
#pragma unroll
            for (int j = 0; j < 4; j++) o_acc[i][j] *= corr;
        }

        // ---- PV via shfl P-broadcast (no smem staging, no syncs) ----
#pragma unroll
        for (int half = 0; half < 2; half++) {
#pragma unroll
            for (int j = 0; j < 4; j++) {
                const int jj = (half << 2) + j;
#pragma unroll 4
                for (int ts = 0; ts < 16; ts++) {
                    int col = (half << 6) + (ts << 2) + j;
                    float4 vv = *(const float4*)&Vs[col][tc << 2];
#pragma unroll
                    for (int i = 0; i < 8; i++) {
                        float p = __shfl_sync(0xffffffffu, acc[i][jj], srcbase | ts);
                        o_acc[i][0] = fmaf(p, vv.x, o_acc[i][0]);
                        o_acc[i][1] = fmaf(p, vv.y, o_acc[i][1]);
                        o_acc[i][2] = fmaf(p, vv.z, o_acc[i][2]);
                        o_acc[i][3] = fmaf(p, vv.w, o_acc[i][3]);
                    }
                }
            }
        }
    }

    // ---- finalize: normalize and store out[b][s][h*64 + d], float4 ----
#pragma unroll
    for (int i = 0; i < 8; i++) {
        float inv = 1.0f / l_i[i];
        int s = r0 + trow + i;
        float* o = out + ((size_t)b * Sn + s) * Hn + h * DH + (tc << 2);
        float4 ov = make_float4(o_acc[i][0] * inv, o_acc[i][1] * inv,
                                o_acc[i][2] * inv, o_acc[i][3] * inv);
        *(float4*)o = ov;
    }
}

// ---------------------------------------------------------------------------
extern "C" void kernel_launch(void* const* d_in, const int* in_sizes, int n_in,
                              void* d_out, int out_size)
{
    const float* hidden  = (const float*)d_in[0];
    const float* context = (const float*)d_in[1];
    const float* amask   = (const float*)d_in[2];
    const float* gate    = (const float*)d_in[3];
    const float* vis     = (const float*)d_in[4];
    const float* Wq      = (const float*)d_in[5];
    const float* bq      = (const float*)d_in[6];
    const float* Wk      = (const float*)d_in[7];
    const float* bk      = (const float*)d_in[8];
    const float* Wv      = (const float*)d_in[9];
    const float* bv      = (const float*)d_in[10];
    const int*   feat    = (const int*)d_in[11];
    const int*   proxp   = (const int*)d_in[12];

    float* out    = (float*)d_out;
    float* scores = out + OUT_ELEMS;

    cudaFuncSetAttribute(attn_kernel,
                         cudaFuncAttributeMaxDynamicSharedMemorySize,
                         (int)ATTN_SMEM);

    qkv_kernel<<<dim3(Sn / 128, Hn / 128, Bn * 3), 256>>>(
        hidden, context, vis, Wq, bq, Wk, bk, Wv, bv, feat);

    attn_kernel<<<dim3(Sn / 128, Bn * NH), 256, ATTN_SMEM>>>(
        gate, amask, feat, proxp, scores, out);
}

// round 5
// speedup vs baseline: 2.0237x; 1.0508x over previous
#include <cuda_runtime.h>
#include <math.h>
#include <stdint.h>

#define Bn 4
#define Sn 1024
#define Hn 768
#define NH 12
#define DH 64
#define NEGV (-100000.0f)

#define OUT_ELEMS (Bn * Sn * Hn)            // 3145728
#define QKV_ELEMS (Bn * NH * Sn * DH)       // 3145728 per tensor

// Scratch (static device globals — allowed; no runtime allocation)
__device__ float g_q[QKV_ELEMS];
__device__ float g_k[QKV_ELEMS];
__device__ float g_v[QKV_ELEMS];

// ---------------------------------------------------------------------------
// helpers: tf32 rounding + m16n8k8 tf32 mma
// ---------------------------------------------------------------------------
__device__ __forceinline__ float tf32_rna(float x) {
    uint32_t u;
    asm("cvt.rna.tf32.f32 %0, %1;" : "=r"(u) : "f"(x));
    return __uint_as_float(u);
}

__device__ __forceinline__ void mma_tf32(float* d,
                                         uint32_t a0, uint32_t a1,
                                         uint32_t a2, uint32_t a3,
                                         uint32_t b0, uint32_t b1) {
    asm volatile(
        "mma.sync.aligned.m16n8k8.row.col.f32.tf32.tf32.f32 "
        "{%0,%1,%2,%3},{%4,%5,%6,%7},{%8,%9},{%0,%1,%2,%3};"
        : "+f"(d[0]), "+f"(d[1]), "+f"(d[2]), "+f"(d[3])
        : "r"(a0), "r"(a1), "r"(a2), "r"(a3), "r"(b0), "r"(b1));
}

// ---------------------------------------------------------------------------
// Kernel 1 (v2): fused positional-add + QKV projection via split-tf32 HMMA
//   x_hi = tf32(x), x_lo = x - x_hi;  acc += hi*hi + hi*lo + lo*hi  (~fp32)
// Block tile 128(m=s) x 128(n=o), BK=32. 8 warps: 4(m) x 2(n), warp 32x64.
// Smem: AsH/AsL/BsH/BsL [128][36] = 73728 B (stride 36 -> conflict-free
// fragment loads: bank = (4g + c) mod 32 bijective for g<8, c<4).
// ---------------------------------------------------------------------------
#define QKV_SMEM (4 * 128 * 36 * sizeof(float))

__global__ __launch_bounds__(256) void qkv_kernel(
    const float* __restrict__ hidden, const float* __restrict__ context,
    const float* __restrict__ vis,
    const float* __restrict__ Wq, const float* __restrict__ bq,
    const float* __restrict__ Wk, const float* __restrict__ bk,
    const float* __restrict__ Wv, const float* __restrict__ bv,
    const int*   __restrict__ feat_len)
{
    extern __shared__ float qsm[];
    float (*AsH)[36] = (float (*)[36])qsm;
    float (*AsL)[36] = AsH + 128;
    float (*BsH)[36] = AsL + 128;
    float (*BsL)[36] = BsH + 128;

    const int z     = blockIdx.z;
    const int b     = z / 3;
    const int which = z - b * 3;

    const float* X    = (which == 0) ? hidden : context;
    const float* W    = (which == 0) ? Wq : (which == 1 ? Wk : Wv);
    const float* bias = (which == 0) ? bq : (which == 1 ? bk : bv);
    float*       OUT  = (which == 0) ? g_q : (which == 1 ? g_k : g_v);

    const int flen = feat_len[b];
    const int r0 = blockIdx.x << 7;          // s base
    const int c0 = blockIdx.y << 7;          // o base
    const int tid  = threadIdx.x;
    const int wid  = tid >> 5;
    const int lane = tid & 31;
    const int g    = lane >> 2;              // 0..7
    const int c    = lane & 3;               // 0..3

    const int wm = (wid & 3) << 5;           // warp m offset: 0,32,64,96
    const int wn = (wid >> 2) << 6;          // warp n offset: 0,64

    const float* Xb = X   + (size_t)b * Sn * Hn;
    const float* Vb = vis + (size_t)b * Sn * Hn;

    float Cacc[2][8][4];
#pragma unroll
    for (int i = 0; i < 2; i++)
#pragma unroll
        for (int j = 0; j < 8; j++)
#pragma unroll
            for (int t = 0; t < 4; t++) Cacc[i][j][t] = 0.0f;

    for (int k0 = 0; k0 < Hn; k0 += 32) {
        __syncthreads();
        // Fill A (X + vis, split) and B (W, split): 1024 float4 each.
#pragma unroll
        for (int it = 0; it < 4; it++) {
            int idx = tid + (it << 8);
            int row = idx >> 3;
            int c4  = (idx & 7) << 2;
            int s   = r0 + row;
            float4 xv = *(const float4*)(Xb + (size_t)s * Hn + k0 + c4);
            if (s < flen) {
                float4 vv = *(const float4*)(Vb + (size_t)s * Hn + k0 + c4);
                xv.x += vv.x; xv.y += vv.y; xv.z += vv.z; xv.w += vv.w;
            }
            float hx = tf32_rna(xv.x), hy = tf32_rna(xv.y),
                  hz = tf32_rna(xv.z), hw = tf32_rna(xv.w);
            AsH[row][c4 + 0] = hx; AsL[row][c4 + 0] = xv.x - hx;
            AsH[row][c4 + 1] = hy; AsL[row][c4 + 1] = xv.y - hy;
            AsH[row][c4 + 2] = hz; AsL[row][c4 + 2] = xv.z - hz;
            AsH[row][c4 + 3] = hw; AsL[row][c4 + 3] = xv.w - hw;

            int o = c0 + row;
            float4 wv = *(const float4*)(W + (size_t)o * Hn + k0 + c4);
            float px = tf32_rna(wv.x), py = tf32_rna(wv.y),
                  pz = tf32_rna(wv.z), pw = tf32_rna(wv.w);
            BsH[row][c4 + 0] = px; BsL[row][c4 + 0] = wv.x - px;
            BsH[row][c4 + 1] = py; BsL[row][c4 + 1] = wv.y - py;
            BsH[row][c4 + 2] = pz; BsL[row][c4 + 2] = wv.z - pz;
            BsH[row][c4 + 3] = pw; BsL[row][c4 + 3] = wv.w - pw;
        }
        __syncthreads();

#pragma unroll
        for (int kk = 0; kk < 4; kk++) {
            const int kb = kk << 3;
            // A fragments (2 m16 tiles), hi + lo
            uint32_t aH[2][4], aL[2][4];
#pragma unroll
            for (int i = 0; i < 2; i++) {
                int ra = wm + (i << 4) + g;
                aH[i][0] = __float_as_uint(AsH[ra    ][kb + c]);
                aH[i][1] = __float_as_uint(AsH[ra + 8][kb + c]);
                aH[i][2] = __float_as_uint(AsH[ra    ][kb + c + 4]);
                aH[i][3] = __float_as_uint(AsH[ra + 8][kb + c + 4]);
                aL[i][0] = __float_as_uint(AsL[ra    ][kb + c]);
                aL[i][1] = __float_as_uint(AsL[ra + 8][kb + c]);
                aL[i][2] = __float_as_uint(AsL[ra    ][kb + c + 4]);
                aL[i][3] = __float_as_uint(AsL[ra + 8][kb + c + 4]);
            }
            // B fragments (8 n8 tiles), hi + lo
            uint32_t bH[8][2], bL[8][2];
#pragma unroll
            for (int j = 0; j < 8; j++) {
                int nb = wn + (j << 3) + g;
                bH[j][0] = __float_as_uint(BsH[nb][kb + c]);
                bH[j][1] = __float_as_uint(BsH[nb][kb + c + 4]);
                bL[j][0] = __float_as_uint(BsL[nb][kb + c]);
                bL[j][1] = __float_as_uint(BsL[nb][kb + c + 4]);
            }
#pragma unroll
            for (int i = 0; i < 2; i++)
#pragma unroll
                for (int j = 0; j < 8; j++) {
                    mma_tf32(Cacc[i][j], aH[i][0], aH[i][1], aH[i][2], aH[i][3],
                             bH[j][0], bH[j][1]);
                    mma_tf32(Cacc[i][j], aH[i][0], aH[i][1], aH[i][2], aH[i][3],
                             bL[j][0], bL[j][1]);
                    mma_tf32(Cacc[i][j], aL[i][0], aL[i][1], aL[i][2], aL[i][3],
                             bH[j][0], bH[j][1]);
                }
        }
    }

    // Epilogue: bias + head-interleaved store [b][h][s][d] (float2 per pair)
#pragma unroll
    for (int j = 0; j < 8; j++) {
        int o  = c0 + wn + (j << 3) + (c << 1);      // even
        float b0v = bias[o], b1v = bias[o + 1];
        int h = o >> 6, d = o & 63;
        float* obase = OUT + (((size_t)b * NH + h) * Sn) * DH + d;
#pragma unroll
        for (int i = 0; i < 2; i++) {
            int s_lo = r0 + wm + (i << 4) + g;
            float2 v0 = make_float2(Cacc[i][j][0] + b0v, Cacc[i][j][1] + b1v);
            float2 v1 = make_float2(Cacc[i][j][2] + b0v, Cacc[i][j][3] + b1v);
            *(float2*)(obase + (size_t)s_lo * DH)       = v0;
            *(float2*)(obase + (size_t)(s_lo + 8) * DH) = v1;
        }
    }
}

// ---------------------------------------------------------------------------
// Kernel 2: fused scores + online softmax + PV (unchanged from R4 — passing)
// ---------------------------------------------------------------------------
#define ATTN_SMEM ((2 * 64 * 132 + 128 * 68) * sizeof(float))

__global__ __launch_bounds__(256, 1) void attn_kernel(
    const float* __restrict__ gate, const float* __restrict__ amask,
    const int*   __restrict__ feat_len, const int* __restrict__ prox_ptr,
    float* __restrict__ scores, float* __restrict__ out)
{
    extern __shared__ float sm[];
    float (*Qt)[132] = (float (*)[132])(sm);
    float (*Kt)[132] = (float (*)[132])(sm + 64 * 132);
    float (*Vs)[68]  = (float (*)[68]) (sm + 2 * 64 * 132);

    const int bh = blockIdx.y;
    const int b  = bh / NH;
    const int h  = bh - b * NH;
    const int r0 = blockIdx.x << 7;
    const int tid  = threadIdx.x;
    const int tr   = tid >> 4;
    const int tc   = tid & 15;
    const int trow = tr << 3;
    const int lane = tid & 31;
    const int srcbase = lane & 16;

    const int P    = prox_ptr[0];
    const int flen = feat_len[b];

    const float* Q = g_q + (size_t)bh * Sn * DH;
    const float* K = g_k + (size_t)bh * Sn * DH;
    const float* V = g_v + (size_t)bh * Sn * DH;
    const float* gate_b = gate + (size_t)b * Sn * Sn;
    const float* am_b   = amask + (size_t)b * Sn;
    float* sc_out = scores + (size_t)bh * Sn * Sn;

#pragma unroll
    for (int it = 0; it < 8; it++) {
        int idx = tid + (it << 8);
        int row = idx >> 4;
        int c4  = (idx & 15) << 2;
        float4 qv = *(const float4*)(Q + (size_t)(r0 + row) * DH + c4);
        Qt[c4 + 0][row] = qv.x; Qt[c4 + 1][row] = qv.y;
        Qt[c4 + 2][row] = qv.z; Qt[c4 + 3][row] = qv.w;
    }

    float m_i[8], l_i[8];
    float o_acc[8][4];
#pragma unroll
    for (int i = 0; i < 8; i++) {
        m_i[i] = -INFINITY; l_i[i] = 0.0f;
#pragma unroll
        for (int j = 0; j < 4; j++) o_acc[i][j] = 0.0f;
    }

    for (int cb = 0; cb < Sn; cb += 128) {
        __syncthreads();
#pragma unroll
        for (int it = 0; it < 8; it++) {
            int idx = tid + (it << 8);
            int row = idx >> 4;
            int c4  = (idx & 15) << 2;
            float4 kv = *(const float4*)(K + (size_t)(cb + row) * DH + c4);
            Kt[c4 + 0][row] = kv.x; Kt[c4 + 1][row] = kv.y;
            Kt[c4 + 2][row] = kv.z; Kt[c4 + 3][row] = kv.w;
            float4 vv = *(const float4*)(V + (size_t)(cb + row) * DH + c4);
            *(float4*)&Vs[row][c4] = vv;
        }
        __syncthreads();

        float acc[8][8];
#pragma unroll
        for (int i = 0; i < 8; i++)
#pragma unroll
            for (int j = 0; j < 8; j++) acc[i][j] = 0.0f;

#pragma unroll 8
        for (int k = 0; k < DH; k++) {
            float4 a0 = *(const float4*)&Qt[k][trow];
            float4 a1 = *(const float4*)&Qt[k][trow + 4];
            float4 b0 = *(const float4*)&Kt[k][tc << 2];
            float4 b1 = *(const float4*)&Kt[k][64 + (tc << 2)];
            float a[8] = {a0.x, a0.y, a0.z, a0.w, a1.x, a1.y, a1.z, a1.w};
            float bb[8] = {b0.x, b0.y, b0.z, b0.w, b1.x, b1.y, b1.z, b1.w};
#pragma unroll
            for (int i = 0; i < 8; i++)
#pragma unroll
                for (int j = 0; j < 8; j++) acc[i][j] = fmaf(a[i], bb[j], acc[i][j]);
        }

        const float4 am0 = *(const float4*)&am_b[cb + (tc << 2)];
        const float4 am1 = *(const float4*)&am_b[cb + 64 + (tc << 2)];
        const float amv[8] = {am0.x, am0.y, am0.z, am0.w, am1.x, am1.y, am1.z, am1.w};
#pragma unroll
        for (int i = 0; i < 8; i++) {
            int r = r0 + trow + i;
            bool rband = (r < P - 1);
            bool rge   = (r >= P);
            const float* grow = gate_b + (size_t)r * Sn;
            float* srow = sc_out + (size_t)r * Sn;
            float4 g0 = *(const float4*)&grow[cb + (tc << 2)];
            float4 g1 = *(const float4*)&grow[cb + 64 + (tc << 2)];
            float gv[8] = {g0.x, g0.y, g0.z, g0.w, g1.x, g1.y, g1.z, g1.w};
#pragma unroll
            for (int half = 0; half < 2; half++) {
#pragma unroll
                for (int j = 0; j < 4; j++) {
                    int jj = (half << 2) + j;
                    int cidx = cb + (half << 6) + (tc << 2) + j;
                    float val = acc[i][jj] * 0.125f;
                    val = val * gv[jj] + amv[jj];
                    bool blk  = rge && (cidx >= P);
                    bool band = rband && ((cidx > r) || (cidx < r - 1));
                    bool m3   = rge && (cidx < flen - 1);
                    if (blk || band || m3) val = NEGV;
                    acc[i][jj] = val;
                }
                float4 sv = make_float4(acc[i][(half << 2) + 0], acc[i][(half << 2) + 1],
                                        acc[i][(half << 2) + 2], acc[i][(half << 2) + 3]);
                *(float4*)&srow[cb + (half << 6) + (tc << 2)] = sv;
            }
        }

#pragma unroll
        for (int i = 0; i < 8; i++) {
            float tmax = acc[i][0];
#pragma unroll
            for (int j = 1; j < 8; j++) tmax = fmaxf(tmax, acc[i][j]);
#pragma unroll
            for (int off = 8; off > 0; off >>= 1)
                tmax = fmaxf(tmax, __shfl_xor_sync(0xffffffffu, tmax, off));
            float m_new = fmaxf(m_i[i], tmax);
            float corr  = __expf(m_i[i] - m_new);
            m_i[i] = m_new;
            float psum = 0.0f;
#pragma unroll
            for (int j = 0; j < 8; j++) {
                float p = __expf(acc[i][j] - m_new);
                acc[i][j] = p;
                psum += p;
            }
#pragma unroll
            for (int off = 8; off > 0; off >>= 1)
                psum += __shfl_xor_sync(0xffffffffu, psum, off);
            l_i[i] = l_i[i] * corr + psum;
#pragma unroll
            for (int j = 0; j < 4; j++) o_acc[i][j] *= corr;
        }

#pragma unroll
        for (int half = 0; half < 2; half++) {
#pragma unroll
            for (int j = 0; j < 4; j++) {
                const int jj = (half << 2) + j;
#pragma unroll 4
                for (int ts = 0; ts < 16; ts++) {
                    int col = (half << 6) + (ts << 2) + j;
                    float4 vv = *(const float4*)&Vs[col][tc << 2];
#pragma unroll
                    for (int i = 0; i < 8; i++) {
                        float p = __shfl_sync(0xffffffffu, acc[i][jj], srcbase | ts);
                        o_acc[i][0] = fmaf(p, vv.x, o_acc[i][0]);
                        o_acc[i][1] = fmaf(p, vv.y, o_acc[i][1]);
                        o_acc[i][2] = fmaf(p, vv.z, o_acc[i][2]);
                        o_acc[i][3] = fmaf(p, vv.w, o_acc[i][3]);
                    }
                }
            }
        }
    }

#pragma unroll
    for (int i = 0; i < 8; i++) {
        float inv = 1.0f / l_i[i];
        int s = r0 + trow + i;
        float* o = out + ((size_t)b * Sn + s) * Hn + h * DH + (tc << 2);
        float4 ov = make_float4(o_acc[i][0] * inv, o_acc[i][1] * inv,
                                o_acc[i][2] * inv, o_acc[i][3] * inv);
        *(float4*)o = ov;
    }
}

// ---------------------------------------------------------------------------
extern "C" void kernel_launch(void* const* d_in, const int* in_sizes, int n_in,
                              void* d_out, int out_size)
{
    const float* hidden  = (const float*)d_in[0];
    const float* context = (const float*)d_in[1];
    const float* amask   = (const float*)d_in[2];
    const float* gate    = (const float*)d_in[3];
    const float* vis     = (const float*)d_in[4];
    const float* Wq      = (const float*)d_in[5];
    const float* bq      = (const float*)d_in[6];
    const float* Wk      = (const float*)d_in[7];
    const float* bk      = (const float*)d_in[8];
    const float* Wv      = (const float*)d_in[9];
    const float* bv      = (const float*)d_in[10];
    const int*   feat    = (const int*)d_in[11];
    const int*   proxp   = (const int*)d_in[12];

    float* out    = (float*)d_out;
    float* scores = out + OUT_ELEMS;

    cudaFuncSetAttribute(qkv_kernel,
                         cudaFuncAttributeMaxDynamicSharedMemorySize,
                         (int)QKV_SMEM);
    cudaFuncSetAttribute(attn_kernel,
                         cudaFuncAttributeMaxDynamicSharedMemorySize,
                         (int)ATTN_SMEM);

    qkv_kernel<<<dim3(Sn / 128, Hn / 128, Bn * 3), 256, QKV_SMEM>>>(
        hidden, context, vis, Wq, bq, Wk, bk, Wv, bv, feat);

    attn_kernel<<<dim3(Sn / 128, Bn * NH), 256, ATTN_SMEM>>>(
        gate, amask, feat, proxp, scores, out);
}